// round 14
// baseline (speedup 1.0000x reference)
#include <cuda_runtime.h>
#include <math.h>

#define LROWS    512
#define NS       8192            // samples per row
#define NREF     8192            // reference grid points
#define NG       (3*NREF)        // 24576 circular-CDF grid points
#define NTHREADS 512
#define NWARPS   (NTHREADS/32)   // 16
#define IPT      (NS/NTHREADS)   // 16 items per thread
#define KPT      (NREF/NTHREADS) // 16 inversion queries per thread (consecutive)

#define STEPG  (3.0f/24575.0f)
#define INVN   (1.0f/8192.0f)

__device__ float g_rowsum[LROWS];
__device__ int   g_done[LROWS];                 // zero-init; self-resetting
__device__ int   g_nrows;                       // zero-init; self-resetting
__device__ float g_h[(size_t)2 * LROWS * NS];   // h1 then h2, 32 MB scratch

// ---------------------------------------------------------------------------
// block-wide exclusive scans (warp shuffle + NWARPS-entry partials)
// ---------------------------------------------------------------------------
__device__ __forceinline__ int block_excl_scan_int(int local_total, int tid, int* s_part)
{
    __syncthreads();
    int lane = tid & 31, wid = tid >> 5;
    int x = local_total;
#pragma unroll
    for (int d = 1; d < 32; d <<= 1) {
        int t = __shfl_up_sync(0xffffffffu, x, d);
        if (lane >= d) x += t;
    }
    if (lane == 31) s_part[wid] = x;
    __syncthreads();
    if (wid == 0) {
        int v = (lane < NWARPS) ? s_part[lane] : 0;
        int y = v;
#pragma unroll
        for (int d = 1; d < NWARPS; d <<= 1) {
            int t = __shfl_up_sync(0xffffffffu, y, d);
            if (lane >= d) y += t;
        }
        if (lane < NWARPS) s_part[lane] = y - v;   // exclusive warp offsets
    }
    __syncthreads();
    return s_part[wid] + (x - local_total);
}

__device__ __forceinline__ float block_excl_scan_float(float local_total, int tid, float* s_part)
{
    __syncthreads();
    int lane = tid & 31, wid = tid >> 5;
    float x = local_total;
#pragma unroll
    for (int d = 1; d < 32; d <<= 1) {
        float t = __shfl_up_sync(0xffffffffu, x, d);
        if (lane >= d) x += t;
    }
    if (lane == 31) s_part[wid] = x;
    __syncthreads();
    if (wid == 0) {
        float v = (lane < NWARPS) ? s_part[lane] : 0.f;
        float y = v;
#pragma unroll
        for (int d = 1; d < NWARPS; d <<= 1) {
            float t = __shfl_up_sync(0xffffffffu, y, d);
            if (lane >= d) y += t;
        }
        if (lane < NWARPS) s_part[lane] = y - v;
    }
    __syncthreads();
    return s_part[wid] + (x - local_total);
}

// exact per-grid-point circular-CDF value. offs convention (post-scatter):
// bucket b occupies [b ? offs[b-1] : 0, offs[b]).
__device__ __forceinline__ float eval_ecdf(int j, const float* xs, const float* cw,
                                           const int* offs)
{
    float xn = fmaf((float)j, STEPG, -1.0f);
    float fi = (float)((j >> 13) - 1);         // period constant
    if (j == NG - 1) fi = floorf(xn);          // xn ~ 2.0 endpoint
    float r = xn - fi;
    int b = (int)(r * 8192.0f);
    b = b < 0 ? 0 : (b > NS - 1 ? NS - 1 : b);
    int lo = b ? offs[b - 1] : 0;
    int hi = offs[b];
    int cnt = lo;
    for (int i = lo; i < hi; i++) cnt += (xs[i] < r) ? 1 : 0;
    int idx = cnt - 1;
    idx = idx < 0 ? 0 : (idx > NS - 2 ? NS - 2 : idx);
    float t = __fdividef(r - xs[idx], xs[idx + 1] - xs[idx]);
    return fi + fmaf(t, cw[idx + 1] - cw[idx], cw[idx]);
}

// exact lower_bound bisection with on-the-fly evaluation -- identical probe
// path and probe VALUES to jnp.searchsorted over the materialized array.
__device__ __forceinline__ int eval_bisect(const float* xs, const float* cw,
                                           const int* offs, float y)
{
    int lo = 0, hi = NG;
#pragma unroll 1
    for (int it = 0; it < 15; it++) {
        int mid = (lo + hi) >> 1;
        float v = eval_ecdf(mid, xs, cw, offs);
        bool c = v < y;
        lo = c ? mid + 1 : lo;
        hi = c ? hi : mid;
    }
    return lo;
}

// ---------------------------------------------------------------------------
// one embedding pass per block: grid = 1024 = 2 datasets x 512 rows
// 2 CTAs/SM (98.3 KB smem each). fully fused: emb -> distance -> scalar.
// ---------------------------------------------------------------------------
__global__ void __launch_bounds__(NTHREADS, 2)
lcot_emb_kernel(const float* __restrict__ x1, const float* __restrict__ w1,
                const float* __restrict__ x2, const float* __restrict__ w2,
                float* __restrict__ out)
{
    extern __shared__ char smem_raw[];
    float* xs   = (float*)smem_raw;            // [NS]
    float* cw   = xs + NS;                     // [NS]
    int*   offs = (int*)(cw + NS);             // [NS+1]

    __shared__ float s_pf[NWARPS];
    __shared__ float s_pf2[NWARPS];
    __shared__ int   s_pi[NWARPS];
    __shared__ float s_alpha;
    __shared__ int   s_second, s_last;

    const int tid = threadIdx.x;
    const int bid = blockIdx.x;
    const int row = bid & (LROWS - 1);
    const int ds  = bid >> 9;
    const size_t base = (size_t)row * NS;
    const float* gx = (ds ? x2 : x1) + base;
    const float* gw = (ds ? w2 : w1) + base;
    float* hout = g_h + (size_t)bid * NS;

    // ---- 1. zero histogram --------------------------------------------------
    for (int i = tid; i <= NS; i += NTHREADS) offs[i] = 0;
    __syncthreads();

    // ---- 2. load (no retention), histogram, alpha partials ------------------
    float pxw = 0.f, pw = 0.f;
    {
        const float4* gx4 = (const float4*)gx;
        const float4* gw4 = (const float4*)gw;
#pragma unroll
        for (int v = 0; v < IPT / 4; v++) {
            float4 X = gx4[tid + v * NTHREADS];
            float4 W = gw4[tid + v * NTHREADS];
            const float* px = (const float*)&X;
            const float* pv = (const float*)&W;
#pragma unroll
            for (int i = 0; i < 4; i++) {
                pxw += px[i] * pv[i]; pw += pv[i];
                int b = (int)(px[i] * 8192.0f);   // exact order-preserving bucket
                if (b > NS - 1) b = NS - 1;
                atomicAdd(&offs[b + 1], 1);
            }
        }
    }
    {
        int lane = tid & 31, wid = tid >> 5;
        float a = pxw, b = pw;
#pragma unroll
        for (int d = 16; d > 0; d >>= 1) {
            a += __shfl_down_sync(0xffffffffu, a, d);
            b += __shfl_down_sync(0xffffffffu, b, d);
        }
        if (lane == 0) { s_pf[wid] = a; s_pf2[wid] = b; }
        __syncthreads();                       // also fences histogram atomics
        if (tid == 0) {
            float sa = 0.f, sb = 0.f;
#pragma unroll
            for (int k = 0; k < NWARPS; k++) { sa += s_pf[k]; sb += s_pf2[k]; }
            s_alpha = sa / sb - 0.5f;
        }
    }

    // ---- 3. exclusive scan of counts -> bucket start offsets ----------------
    {
        int c[IPT]; int runc = 0;
#pragma unroll
        for (int j = 0; j < IPT; j++) {
            runc += offs[1 + tid * IPT + j];
            c[j] = runc;
        }
        int exc = block_excl_scan_int(runc, tid, s_pi);
#pragma unroll
        for (int j = 0; j < IPT; j++) offs[1 + tid * IPT + j] = exc + c[j];
        __syncthreads();
    }

    // ---- 4. scatter (reload inputs; offs consumed in place as cursors) ------
    // atomicAdd(&offs[b],1) returns the next slot; afterwards offs[b] = END of
    // bucket b, so bucket b = [b ? offs[b-1] : 0, offs[b]).
    {
        const float4* gx4 = (const float4*)gx;
        const float4* gw4 = (const float4*)gw;
#pragma unroll
        for (int v = 0; v < IPT / 4; v++) {
            float4 X = gx4[tid + v * NTHREADS];
            float4 W = gw4[tid + v * NTHREADS];
            const float* px = (const float*)&X;
            const float* pv = (const float*)&W;
#pragma unroll
            for (int i = 0; i < 4; i++) {
                int b = (int)(px[i] * 8192.0f);
                if (b > NS - 1) b = NS - 1;
                int pos = atomicAdd(&offs[b], 1);
                xs[pos] = px[i];
                cw[pos] = pv[i];
            }
        }
        __syncthreads();
    }

    // ---- 5. per-bucket insertion sort (avg occupancy 1) ---------------------
    for (int b = tid; b < NS; b += NTHREADS) {
        int s = b ? offs[b - 1] : 0;
        int e = offs[b];
        for (int i = s + 1; i < e; i++) {
            float kx = xs[i], kv = cw[i];
            int j = i - 1;
            while (j >= s && xs[j] > kx) { xs[j+1] = xs[j]; cw[j+1] = cw[j]; j--; }
            xs[j+1] = kx; cw[j+1] = kv;
        }
    }
    __syncthreads();

    // ---- 6. cumsum of sorted weights -> cdf (in place) ----------------------
    {
        float v[IPT]; float runf = 0.f;
#pragma unroll
        for (int j = 0; j < IPT; j++) { runf += cw[tid * IPT + j]; v[j] = runf; }
        float excf = block_excl_scan_float(runf, tid, s_pf);
#pragma unroll
        for (int j = 0; j < IPT; j++) cw[tid * IPT + j] = excf + v[j];
        __syncthreads();
    }

    // ---- 7. invert CDF: bracketed exact inversion, ecdf evaluated on the fly.
    // Every probe value is the exact eval_ecdf (bit-identical to materializing
    // the array), so landings match jnp.searchsorted exactly. Fence landings
    // bracket the 15 intermediate ones (landings monotone in y). Safe bracket
    // (no possible non-monotone index {8192,16384,NG-1} inside) => region
    // monotone => a forward MERGE sweep (queries sorted) finds each landing as
    // the unique crossing, evaluating each grid point once and capturing
    // e0/e1 in flight. Unsafe brackets: exact per-query bisect fallback.
    const float alpha_r = s_alpha;
    const int k0 = tid * KPT;
    {
        float y0 = (float)k0 * INVN - alpha_r;
        int posA = eval_bisect(xs, cw, offs, y0);
        int posB = __shfl_down_sync(0xffffffffu, posA, 1);
        if ((tid & 31) == 31)
            posB = eval_bisect(xs, cw, offs, (float)(k0 + KPT) * INVN - alpha_r);

        bool unsafe = (8192  >= posA && 8192  <= posB) ||
                      (16384 >= posA && 16384 <= posB) ||
                      (NG - 1 >= posA && NG - 1 <= posB);

        float4* hv = (float4*)(hout + k0);
        float o[4];

        if (!unsafe) {
            int i = posA;
            int pm1 = posA - 1; if (pm1 < 0) pm1 = 0;
            float e_prev = eval_ecdf(pm1, xs, cw, offs);
            float e_i    = eval_ecdf(i,   xs, cw, offs);
#pragma unroll 1
            for (int q = 0; q < KPT; q++) {
                float yq = (float)(k0 + q) * INVN - alpha_r;
                while (e_i < yq) {            // terminates: e[posB] >= y_upper > yq
                    e_prev = e_i;
                    i++;
                    e_i = eval_ecdf(i, xs, cw, offs);
                }
                int   idx; float e0, e1;
                if (i == 0) { idx = 0; e0 = e_i; e1 = eval_ecdf(1, xs, cw, offs); }
                else        { idx = i - 1; e0 = e_prev; e1 = e_i; }
                float xn0 = fmaf((float)idx,       STEPG, -1.0f);
                float xn1 = fmaf((float)(idx + 1), STEPG, -1.0f);
                float t   = __fdividef(yq - e0, e1 - e0);
                float xk  = (float)(k0 + q) * INVN;
                o[q & 3] = fmaf(t, xn1 - xn0, xn0) - xk;
                if ((q & 3) == 3)
                    hv[q >> 2] = make_float4(o[0], o[1], o[2], o[3]);
            }
        } else {
#pragma unroll 1
            for (int q = 0; q < KPT; q++) {
                float yq = (float)(k0 + q) * INVN - alpha_r;
                int pos = eval_bisect(xs, cw, offs, yq);
                int idx = pos - 1;
                idx = idx < 0 ? 0 : (idx > NG - 2 ? NG - 2 : idx);
                float e0 = eval_ecdf(idx,     xs, cw, offs);
                float e1 = eval_ecdf(idx + 1, xs, cw, offs);
                float xn0 = fmaf((float)idx,       STEPG, -1.0f);
                float xn1 = fmaf((float)(idx + 1), STEPG, -1.0f);
                float t   = __fdividef(yq - e0, e1 - e0);
                float xk  = (float)(k0 + q) * INVN;
                o[q & 3] = fmaf(t, xn1 - xn0, xn0) - xk;
                if ((q & 3) == 3)
                    hv[q >> 2] = make_float4(o[0], o[1], o[2], o[3]);
            }
        }
    }

    // ---- 8. fused distance (2nd finisher per row) ---------------------------
    __threadfence();
    __syncthreads();                           // all h writes of block done
    if (tid == 0) {
        int old = atomicAdd(&g_done[row], 1);
        s_second = (old == 1);
        if (old == 1) g_done[row] = 0;         // self-reset for graph replays
        s_last = 0;
    }
    __syncthreads();
    if (s_second) {
        __threadfence();                       // acquire partner's h writes
        const float* hA = g_h + (size_t)row * NS;
        const float* hB = g_h + (size_t)(LROWS + row) * NS;
        float acc = 0.f;
#pragma unroll
        for (int v = 0; v < KPT / 4; v++) {
            float4 A = *(const float4*)(hA + k0 + v * 4);
            float4 B = *(const float4*)(hB + k0 + v * 4);
            const float* pa = (const float*)&A;
            const float* pb = (const float*)&B;
#pragma unroll
            for (int i = 0; i < 4; i++) {
                float d = fabsf(pb[i] - pa[i]);
                float m = fminf(d, 1.0f - d);
                acc = fmaf(m, m, acc);
            }
        }
        int lane = tid & 31, wid = tid >> 5;
#pragma unroll
        for (int d = 16; d > 0; d >>= 1)
            acc += __shfl_down_sync(0xffffffffu, acc, d);
        if (lane == 0) s_pf[wid] = acc;
        __syncthreads();
        if (tid == 0) {
            float s = 0.f;
#pragma unroll
            for (int k = 0; k < NWARPS; k++) s += s_pf[k];
            g_rowsum[row] = s;
            __threadfence();                   // release rowsum
            int old2 = atomicAdd(&g_nrows, 1);
            s_last = (old2 == LROWS - 1);
            if (s_last) g_nrows = 0;           // self-reset for graph replays
        }
        __syncthreads();

        // ---- 9. fused finalize (the very last finisher block) ---------------
        if (s_last) {
            __threadfence();                   // acquire all rowsums
            float* red = (float*)smem_raw;     // reuse smem (xs region)
            red[tid] = g_rowsum[tid];          // NTHREADS == LROWS == 512
            __syncthreads();
            for (int s = LROWS / 2; s > 0; s >>= 1) {
                if (tid < s) red[tid] += red[tid + s];
                __syncthreads();
            }
            if (tid == 0) out[0] = sqrtf(red[0] / (float)LROWS);
        }
    }
}

extern "C" void kernel_launch(void* const* d_in, const int* in_sizes, int n_in,
                              void* d_out, int out_size)
{
    const float* x1 = (const float*)d_in[0];
    const float* w1 = (const float*)d_in[1];
    const float* x2 = (const float*)d_in[2];
    const float* w2 = (const float*)d_in[3];
    float* out = (float*)d_out;

    size_t dyn = (size_t)(2 * NS) * sizeof(float)
               + (size_t)(NS + 1) * sizeof(int);   // 98308 B -> 2 CTAs/SM

    cudaFuncSetAttribute(lcot_emb_kernel,
                         cudaFuncAttributeMaxDynamicSharedMemorySize, (int)dyn);

    lcot_emb_kernel<<<2 * LROWS, NTHREADS, dyn>>>(x1, w1, x2, w2, out);
}

// round 15
// speedup vs baseline: 2.6543x; 2.6543x over previous
#include <cuda_runtime.h>
#include <math.h>

#define LROWS    512
#define NS       8192            // samples per row
#define NREF     8192            // reference grid points
#define NG       (3*NREF)        // 24576 circular-CDF grid points
#define NTHREADS 1024
#define IPT      (NS/NTHREADS)   // 8 items per thread
#define KPT      (NREF/NTHREADS) // 8 inversion queries per thread (consecutive)

#define STEPG  (3.0f/24575.0f)
#define INVN   (1.0f/8192.0f)

__device__ float g_rowsum[LROWS];
__device__ int   g_done[LROWS];                 // zero-init; self-resetting
__device__ int   g_nrows;                       // zero-init; self-resetting
__device__ float g_h[(size_t)2 * LROWS * NS];   // h1 then h2, 32 MB scratch

// ---------------------------------------------------------------------------
// block-wide exclusive scans (warp shuffle + 32-entry partials)
// ---------------------------------------------------------------------------
__device__ __forceinline__ int block_excl_scan_int(int local_total, int tid, int* s_part)
{
    __syncthreads();
    int lane = tid & 31, wid = tid >> 5;
    int x = local_total;
#pragma unroll
    for (int d = 1; d < 32; d <<= 1) {
        int t = __shfl_up_sync(0xffffffffu, x, d);
        if (lane >= d) x += t;
    }
    if (lane == 31) s_part[wid] = x;
    __syncthreads();
    if (wid == 0) {
        int v = s_part[lane];
        int y = v;
#pragma unroll
        for (int d = 1; d < 32; d <<= 1) {
            int t = __shfl_up_sync(0xffffffffu, y, d);
            if (lane >= d) y += t;
        }
        s_part[lane] = y - v;                  // exclusive warp offsets
    }
    __syncthreads();
    return s_part[wid] + (x - local_total);
}

__device__ __forceinline__ float block_excl_scan_float(float local_total, int tid, float* s_part)
{
    __syncthreads();
    int lane = tid & 31, wid = tid >> 5;
    float x = local_total;
#pragma unroll
    for (int d = 1; d < 32; d <<= 1) {
        float t = __shfl_up_sync(0xffffffffu, x, d);
        if (lane >= d) x += t;
    }
    if (lane == 31) s_part[wid] = x;
    __syncthreads();
    if (wid == 0) {
        float v = s_part[lane];
        float y = v;
#pragma unroll
        for (int d = 1; d < 32; d <<= 1) {
            float t = __shfl_up_sync(0xffffffffu, y, d);
            if (lane >= d) y += t;
        }
        s_part[lane] = y - v;
    }
    __syncthreads();
    return s_part[wid] + (x - local_total);
}

// exact per-grid-point circular-CDF value. offs convention (post-scatter,
// in-place consumed): bucket b = [b ? offs[b-1] : 0, offs[b]).
__device__ __forceinline__ float eval_ecdf(int j, const float* xs, const float* cw,
                                           const int* offs)
{
    float xn = fmaf((float)j, STEPG, -1.0f);
    float fi = (float)((j >> 13) - 1);         // period constant
    if (j == NG - 1) fi = floorf(xn);          // xn ~ 2.0 endpoint
    float r = xn - fi;
    int b = (int)(r * 8192.0f);
    b = b < 0 ? 0 : (b > NS - 1 ? NS - 1 : b);
    int lo = b ? offs[b - 1] : 0;
    int hi = offs[b];
    int cnt = lo;
    for (int i = lo; i < hi; i++) cnt += (xs[i] < r) ? 1 : 0;
    int idx = cnt - 1;
    idx = idx < 0 ? 0 : (idx > NS - 2 ? NS - 2 : idx);
    float t = __fdividef(r - xs[idx], xs[idx + 1] - xs[idx]);
    return fi + fmaf(t, cw[idx + 1] - cw[idx], cw[idx]);
}

// full exact lower_bound bisection -- identical probe path to jnp.searchsorted.
__device__ __forceinline__ int full_bisect(const float* ecdf, float y)
{
    int lo = 0, hi = NG;
#pragma unroll
    for (int it = 0; it < 15; it++) {
        int mid = (lo + hi) >> 1;
        bool c = ecdf[mid] < y;
        lo = c ? mid + 1 : lo;
        hi = c ? hi : mid;
    }
    return lo;
}

// value-driven bisection with on-the-fly evaluation; stashes every probed
// value into ecdf[]. The stashed indices cover every probe outside
// [jlo, jhi] made by any query landing inside (covering argument: such a
// probe's fixed-tree node contains both the probe and jlo (or jhi), hence
// lies on the jlo- / jhi-path at that depth).
__device__ __forceinline__ int bisect_eval_stash(float* ecdf, const float* xs,
                                                 const float* cw, const int* offs,
                                                 float y)
{
    int lo = 0, hi = NG;
#pragma unroll
    for (int it = 0; it < 15; it++) {
        int mid = (lo + hi) >> 1;
        float v = eval_ecdf(mid, xs, cw, offs);
        ecdf[mid] = v;
        bool c = v < y;
        lo = c ? mid + 1 : lo;
        hi = c ? hi : mid;
    }
    return lo;
}

// ---------------------------------------------------------------------------
// one embedding pass per block: grid = 1024 = 2 datasets x 512 rows
// fully fused: emb -> per-row distance (2nd finisher) -> final scalar (last)
// ---------------------------------------------------------------------------
__global__ void __launch_bounds__(NTHREADS, 1)
lcot_emb_kernel(const float* __restrict__ x1, const float* __restrict__ w1,
                const float* __restrict__ x2, const float* __restrict__ w2,
                float* __restrict__ out)
{
    extern __shared__ char smem_raw[];
    float* xs   = (float*)smem_raw;            // [NS]
    float* cw   = xs + NS;                     // [NS]
    int*   offs = (int*)(cw + NS);             // [NS+1]
    float* ecdf = (float*)(offs + (NS + 1));   // [NG]

    __shared__ float s_pf[32];
    __shared__ float s_pf2[32];
    __shared__ int   s_pi[32];
    __shared__ float s_alpha;
    __shared__ int   s_jlo, s_jhi;
    __shared__ int   s_second, s_last;

    const int tid = threadIdx.x;
    const int bid = blockIdx.x;
    const int row = bid & (LROWS - 1);
    const int ds  = bid >> 9;
    const size_t base = (size_t)row * NS;
    const float* gx = (ds ? x2 : x1) + base;
    const float* gw = (ds ? w2 : w1) + base;
    float* hout = g_h + (size_t)bid * NS;

    // ---- 1. zero histogram --------------------------------------------------
    for (int i = tid; i <= NS; i += NTHREADS) offs[i] = 0;
    __syncthreads();

    // ---- 2. vectorized load, histogram, alpha partials ----------------------
    float lx[IPT], lw[IPT];
    float pxw = 0.f, pw = 0.f;
    {
        const float4* gx4 = (const float4*)gx;
        const float4* gw4 = (const float4*)gw;
#pragma unroll
        for (int v = 0; v < IPT / 4; v++) {
            float4 X = gx4[tid + v * NTHREADS];
            float4 W = gw4[tid + v * NTHREADS];
            lx[v*4+0] = X.x; lx[v*4+1] = X.y; lx[v*4+2] = X.z; lx[v*4+3] = X.w;
            lw[v*4+0] = W.x; lw[v*4+1] = W.y; lw[v*4+2] = W.z; lw[v*4+3] = W.w;
        }
#pragma unroll
        for (int i = 0; i < IPT; i++) {
            pxw += lx[i] * lw[i]; pw += lw[i];
            int b = (int)(lx[i] * 8192.0f);    // exact order-preserving bucket
            if (b > NS - 1) b = NS - 1;
            atomicAdd(&offs[b + 1], 1);
        }
    }
    {
        int lane = tid & 31, wid = tid >> 5;
        float a = pxw, b = pw;
#pragma unroll
        for (int d = 16; d > 0; d >>= 1) {
            a += __shfl_down_sync(0xffffffffu, a, d);
            b += __shfl_down_sync(0xffffffffu, b, d);
        }
        if (lane == 0) { s_pf[wid] = a; s_pf2[wid] = b; }
        __syncthreads();                       // also fences histogram atomics
        if (tid == 0) {
            float sa = 0.f, sb = 0.f;
#pragma unroll
            for (int k = 0; k < 32; k++) { sa += s_pf[k]; sb += s_pf2[k]; }
            s_alpha = sa / sb - 0.5f;
        }
    }

    // ---- 3. exclusive scan of counts -> bucket START offsets ----------------
    // post-scan: offs[b] = start of bucket b (offs[0] = 0)
    {
        int c[IPT]; int runc = 0;
#pragma unroll
        for (int j = 0; j < IPT; j++) {
            runc += offs[1 + tid * IPT + j];
            c[j] = runc;
        }
        int exc = block_excl_scan_int(runc, tid, s_pi);
#pragma unroll
        for (int j = 0; j < IPT; j++) offs[1 + tid * IPT + j] = exc + c[j];
        __syncthreads();
    }

    // ---- 4. scatter: offs consumed in place as cursors ----------------------
    // atomicAdd(&offs[b],1) returns the next slot; post-scatter offs[b] = END
    // of bucket b, so bucket b = [b ? offs[b-1] : 0, offs[b]).
    {
#pragma unroll
        for (int i = 0; i < IPT; i++) {
            float x = lx[i];
            int b = (int)(x * 8192.0f);
            if (b > NS - 1) b = NS - 1;
            int pos = atomicAdd(&offs[b], 1);
            xs[pos] = x;
            cw[pos] = lw[i];
        }
        __syncthreads();
    }

    // ---- 5. per-bucket insertion sort (avg occupancy 1) ---------------------
    for (int b = tid; b < NS; b += NTHREADS) {
        int s = b ? offs[b - 1] : 0;
        int e = offs[b];
        for (int i = s + 1; i < e; i++) {
            float kx = xs[i], kv = cw[i];
            int j = i - 1;
            while (j >= s && xs[j] > kx) { xs[j+1] = xs[j]; cw[j+1] = cw[j]; j--; }
            xs[j+1] = kx; cw[j+1] = kv;
        }
    }
    __syncthreads();

    // ---- 6. cumsum of sorted weights -> cdf (in place) ----------------------
    {
        float v[IPT]; float runf = 0.f;
#pragma unroll
        for (int j = 0; j < IPT; j++) { runf += cw[tid * IPT + j]; v[j] = runf; }
        float excf = block_excl_scan_float(runf, tid, s_pf);
#pragma unroll
        for (int j = 0; j < IPT; j++) cw[tid * IPT + j] = excf + v[j];
        __syncthreads();
    }

    // ---- 7a. overlap: stashing mini-bisections || speculative raster --------
    const float alpha_r = s_alpha;
    int spec_lo, spec_hi;
    {
        int est = (int)((1.0f - alpha_r) * (24575.0f / 3.0f));
        spec_lo = est - 288;         if (spec_lo < 0) spec_lo = 0;
        spec_hi = est + NS + 576;    if (spec_hi > NG - 1) spec_hi = NG - 1;
        if (tid == 0)
            s_jlo = bisect_eval_stash(ecdf, xs, cw, offs, 0.0f - alpha_r);
        else if (tid == 32)
            s_jhi = bisect_eval_stash(ecdf, xs, cw, offs,
                                      (float)(NREF - 1) * INVN - alpha_r);
        else if (tid >= 64) {
            for (int j = spec_lo + (tid - 64); j <= spec_hi; j += NTHREADS - 64)
                ecdf[j] = eval_ecdf(j, xs, cw, offs);
        }
    }
    __syncthreads();

    // ---- 7b. gap fill: only the (normally empty) ranges the speculative
    // window missed: [jstart, spec_lo) and (spec_hi, jend] ---------------------
    {
        int jstart = s_jlo - 1; if (jstart < 0) jstart = 0;
        int jend   = s_jhi;     if (jend > NG - 1) jend = NG - 1;
        for (int j = jstart + tid; j < spec_lo; j += NTHREADS)
            ecdf[j] = eval_ecdf(j, xs, cw, offs);
        for (int j = spec_hi + 1 + tid; j <= jend; j += NTHREADS)
            ecdf[j] = eval_ecdf(j, xs, cw, offs);
    }
    __syncthreads();

    // ---- 8. invert CDF: bracketed exact inversion ---------------------------
    // Fence landings bracket the 7 intermediate ones (landings monotone in y).
    // Safe bracket (no drop index in [posA, posB]) => region monotone =>
    // landing = posA + #{i in [posA,posB): ecdf[i] < y} (count sweep, one LDS
    // per bracket element shared by all 7 queries). Wide or unsafe brackets
    // fall back to bisection -- all paths land identically.
    const int k0 = tid * KPT;
    {
        float y0 = (float)k0 * INVN - alpha_r;
        int posA = full_bisect(ecdf, y0);
        int posB = __shfl_down_sync(0xffffffffu, posA, 1);
        if ((tid & 31) == 31) {
            posB = (tid == NTHREADS - 1)
                 ? s_jhi
                 : full_bisect(ecdf, (float)(k0 + KPT) * INVN - alpha_r);
        }

        float yq[KPT];
#pragma unroll
        for (int q = 1; q < KPT; q++)
            yq[q] = (float)(k0 + q) * INVN - alpha_r;

        int pos[KPT];
        pos[0] = posA;
        int w = posB - posA;
        bool unsafe = (8192  >= posA && 8192  <= posB) ||
                      (16384 >= posA && 16384 <= posB) ||
                      (NG - 1 >= posA && NG - 1 <= posB);
        if (!unsafe && w <= 64) {
            // count sweep: sequential LDS, each value serves all 7 queries
            int cnt[KPT];
#pragma unroll
            for (int q = 1; q < KPT; q++) cnt[q] = 0;
            for (int i = posA; i < posB; i++) {
                float e = ecdf[i];
#pragma unroll
                for (int q = 1; q < KPT; q++) cnt[q] += (e < yq[q]) ? 1 : 0;
            }
#pragma unroll
            for (int q = 1; q < KPT; q++) pos[q] = posA + cnt[q];
        } else if (!unsafe) {
            // wide monotone bracket: restricted bisection (identical landing)
            int hi_q[KPT];
#pragma unroll
            for (int q = 1; q < KPT; q++) { pos[q] = posA; hi_q[q] = posB; }
            while (w > 0) {
#pragma unroll
                for (int q = 1; q < KPT; q++) {
                    if (pos[q] < hi_q[q]) {
                        int mid = (pos[q] + hi_q[q]) >> 1;
                        bool c = ecdf[mid] < yq[q];
                        pos[q]  = c ? mid + 1 : pos[q];
                        hi_q[q] = c ? hi_q[q] : mid;
                    }
                }
                w >>= 1;
            }
        } else {
            // bracket touches a possible non-monotone index: exact fallback
#pragma unroll
            for (int q = 1; q < KPT; q++)
                pos[q] = full_bisect(ecdf, yq[q]);
        }

        float4 outv[KPT / 4];
        float* outf = (float*)outv;
#pragma unroll
        for (int q = 0; q < KPT; q++) {
            int k = k0 + q;
            float xk = (float)k * INVN;
            float yv = xk - alpha_r;
            int idx = pos[q] - 1;
            idx = idx < 0 ? 0 : (idx > NG - 2 ? NG - 2 : idx);
            float e0 = ecdf[idx], e1 = ecdf[idx + 1];
            float xn0 = fmaf((float)idx,       STEPG, -1.0f);
            float xn1 = fmaf((float)(idx + 1), STEPG, -1.0f);
            float t = __fdividef(yv - e0, e1 - e0);
            outf[q] = fmaf(t, xn1 - xn0, xn0) - xk;
        }
        float4* hv = (float4*)(hout + k0);
        hv[0] = outv[0];
        hv[1] = outv[1];
    }

    // ---- 9. fused distance (2nd finisher per row) ---------------------------
    __threadfence();
    __syncthreads();                           // all h writes of block done
    if (tid == 0) {
        int old = atomicAdd(&g_done[row], 1);
        s_second = (old == 1);
        if (old == 1) g_done[row] = 0;         // self-reset for graph replays
        s_last = 0;
    }
    __syncthreads();
    if (s_second) {
        __threadfence();                       // acquire partner's h writes
        const float* hA = g_h + (size_t)row * NS;
        const float* hB = g_h + (size_t)(LROWS + row) * NS;
        float4 a0 = *(const float4*)(hA + k0);
        float4 a1 = *(const float4*)(hA + k0 + 4);
        float4 b0 = *(const float4*)(hB + k0);
        float4 b1 = *(const float4*)(hB + k0 + 4);
        float acc = 0.f;
        {
            const float* pa = (const float*)&a0;
            const float* pb = (const float*)&b0;
#pragma unroll
            for (int i = 0; i < 4; i++) {
                float d = fabsf(pb[i] - pa[i]);
                float m = fminf(d, 1.0f - d);
                acc = fmaf(m, m, acc);
            }
            pa = (const float*)&a1; pb = (const float*)&b1;
#pragma unroll
            for (int i = 0; i < 4; i++) {
                float d = fabsf(pb[i] - pa[i]);
                float m = fminf(d, 1.0f - d);
                acc = fmaf(m, m, acc);
            }
        }
        int lane = tid & 31, wid = tid >> 5;
#pragma unroll
        for (int d = 16; d > 0; d >>= 1)
            acc += __shfl_down_sync(0xffffffffu, acc, d);
        if (lane == 0) s_pf[wid] = acc;
        __syncthreads();
        if (tid == 0) {
            float s = 0.f;
#pragma unroll
            for (int k = 0; k < 32; k++) s += s_pf[k];
            g_rowsum[row] = s;
            __threadfence();                   // release rowsum
            int old2 = atomicAdd(&g_nrows, 1);
            s_last = (old2 == LROWS - 1);
            if (s_last) g_nrows = 0;           // self-reset for graph replays
        }
        __syncthreads();

        // ---- 10. fused finalize (the very last finisher block) --------------
        if (s_last) {
            __threadfence();                   // acquire all rowsums
            float* red = (float*)smem_raw;     // reuse smem (xs region)
            if (tid < LROWS) red[tid] = g_rowsum[tid];
            __syncthreads();
            for (int s = LROWS / 2; s > 0; s >>= 1) {
                if (tid < s) red[tid] += red[tid + s];
                __syncthreads();
            }
            if (tid == 0) out[0] = sqrtf(red[0] / (float)LROWS);
        }
    }
}

extern "C" void kernel_launch(void* const* d_in, const int* in_sizes, int n_in,
                              void* d_out, int out_size)
{
    const float* x1 = (const float*)d_in[0];
    const float* w1 = (const float*)d_in[1];
    const float* x2 = (const float*)d_in[2];
    const float* w2 = (const float*)d_in[3];
    float* out = (float*)d_out;

    size_t dyn = (size_t)(2 * NS) * sizeof(float)
               + (size_t)(NS + 1) * sizeof(int)
               + (size_t)NG * sizeof(float);   // 196612 B

    cudaFuncSetAttribute(lcot_emb_kernel,
                         cudaFuncAttributeMaxDynamicSharedMemorySize, (int)dyn);

    lcot_emb_kernel<<<2 * LROWS, NTHREADS, dyn>>>(x1, w1, x2, w2, out);
}

// round 16
// speedup vs baseline: 2.6595x; 1.0019x over previous
#include <cuda_runtime.h>
#include <math.h>

#define LROWS    512
#define NS       8192            // samples per row
#define NREF     8192            // reference grid points
#define NG       (3*NREF)        // 24576 circular-CDF grid points
#define NTHREADS 1024
#define IPT      (NS/NTHREADS)   // 8 items per thread
#define KPT      (NREF/NTHREADS) // 8 inversion queries per thread (consecutive)

#define STEPG  (3.0f/24575.0f)
#define INVN   (1.0f/8192.0f)

__device__ float g_rowsum[LROWS];
__device__ int   g_done[LROWS];                 // zero-init; self-resetting
__device__ int   g_nrows;                       // zero-init; self-resetting
__device__ float g_h[(size_t)2 * LROWS * NS];   // h1 then h2, 32 MB scratch

// ---------------------------------------------------------------------------
// block-wide exclusive scans (warp shuffle + 32-entry partials)
// ---------------------------------------------------------------------------
__device__ __forceinline__ int block_excl_scan_int(int local_total, int tid, int* s_part)
{
    __syncthreads();
    int lane = tid & 31, wid = tid >> 5;
    int x = local_total;
#pragma unroll
    for (int d = 1; d < 32; d <<= 1) {
        int t = __shfl_up_sync(0xffffffffu, x, d);
        if (lane >= d) x += t;
    }
    if (lane == 31) s_part[wid] = x;
    __syncthreads();
    if (wid == 0) {
        int v = s_part[lane];
        int y = v;
#pragma unroll
        for (int d = 1; d < 32; d <<= 1) {
            int t = __shfl_up_sync(0xffffffffu, y, d);
            if (lane >= d) y += t;
        }
        s_part[lane] = y - v;                  // exclusive warp offsets
    }
    __syncthreads();
    return s_part[wid] + (x - local_total);
}

__device__ __forceinline__ float block_excl_scan_float(float local_total, int tid, float* s_part)
{
    __syncthreads();
    int lane = tid & 31, wid = tid >> 5;
    float x = local_total;
#pragma unroll
    for (int d = 1; d < 32; d <<= 1) {
        float t = __shfl_up_sync(0xffffffffu, x, d);
        if (lane >= d) x += t;
    }
    if (lane == 31) s_part[wid] = x;
    __syncthreads();
    if (wid == 0) {
        float v = s_part[lane];
        float y = v;
#pragma unroll
        for (int d = 1; d < 32; d <<= 1) {
            float t = __shfl_up_sync(0xffffffffu, y, d);
            if (lane >= d) y += t;
        }
        s_part[lane] = y - v;
    }
    __syncthreads();
    return s_part[wid] + (x - local_total);
}

// exact per-grid-point circular-CDF value. offs convention (post-scatter,
// in-place consumed): bucket b = [b ? offs[b-1] : 0, offs[b]).
__device__ __forceinline__ float eval_ecdf(int j, const float* xs, const float* cw,
                                           const int* offs)
{
    float xn = fmaf((float)j, STEPG, -1.0f);
    float fi = (float)((j >> 13) - 1);         // period constant
    if (j == NG - 1) fi = floorf(xn);          // xn ~ 2.0 endpoint
    float r = xn - fi;
    int b = (int)(r * 8192.0f);
    b = b < 0 ? 0 : (b > NS - 1 ? NS - 1 : b);
    int lo = b ? offs[b - 1] : 0;
    int hi = offs[b];
    int cnt = lo;
    for (int i = lo; i < hi; i++) cnt += (xs[i] < r) ? 1 : 0;
    int idx = cnt - 1;
    idx = idx < 0 ? 0 : (idx > NS - 2 ? NS - 2 : idx);
    float t = __fdividef(r - xs[idx], xs[idx + 1] - xs[idx]);
    return fi + fmaf(t, cw[idx + 1] - cw[idx], cw[idx]);
}

// full exact lower_bound bisection -- identical probe path to jnp.searchsorted.
__device__ __forceinline__ int full_bisect(const float* ecdf, float y)
{
    int lo = 0, hi = NG;
#pragma unroll
    for (int it = 0; it < 15; it++) {
        int mid = (lo + hi) >> 1;
        bool c = ecdf[mid] < y;
        lo = c ? mid + 1 : lo;
        hi = c ? hi : mid;
    }
    return lo;
}

// value-driven bisection with on-the-fly evaluation; stashes every probed
// value into ecdf[]. The stashed indices cover every probe outside
// [jlo, jhi] made by any query landing inside (covering argument: such a
// probe's fixed-tree node contains both the probe and jlo (or jhi), hence
// lies on the jlo- / jhi-path at that depth).
__device__ __forceinline__ int bisect_eval_stash(float* ecdf, const float* xs,
                                                 const float* cw, const int* offs,
                                                 float y)
{
    int lo = 0, hi = NG;
#pragma unroll
    for (int it = 0; it < 15; it++) {
        int mid = (lo + hi) >> 1;
        float v = eval_ecdf(mid, xs, cw, offs);
        ecdf[mid] = v;
        bool c = v < y;
        lo = c ? mid + 1 : lo;
        hi = c ? hi : mid;
    }
    return lo;
}

// ---------------------------------------------------------------------------
// one embedding pass per block: grid = 1024 = 2 datasets x 512 rows
// fully fused: emb -> per-row distance (2nd finisher) -> final scalar (last)
// ---------------------------------------------------------------------------
__global__ void __launch_bounds__(NTHREADS, 1)
lcot_emb_kernel(const float* __restrict__ x1, const float* __restrict__ w1,
                const float* __restrict__ x2, const float* __restrict__ w2,
                float* __restrict__ out)
{
    extern __shared__ char smem_raw[];
    float* xs   = (float*)smem_raw;            // [NS]
    float* cw   = xs + NS;                     // [NS]
    int*   offs = (int*)(cw + NS);             // [NS+1]
    float* ecdf = (float*)(offs + (NS + 1));   // [NG]

    __shared__ float s_pf[32];
    __shared__ float s_pf2[32];
    __shared__ int   s_pi[32];
    __shared__ int   s_wfence[33];             // per-warp lane0 posA + sentinel
    __shared__ float s_alpha;
    __shared__ int   s_jlo, s_jhi;
    __shared__ int   s_second, s_last;

    const int tid = threadIdx.x;
    const int bid = blockIdx.x;
    const int row = bid & (LROWS - 1);
    const int ds  = bid >> 9;
    const size_t base = (size_t)row * NS;
    const float* gx = (ds ? x2 : x1) + base;
    const float* gw = (ds ? w2 : w1) + base;
    float* hout = g_h + (size_t)bid * NS;

    // ---- 1. zero histogram --------------------------------------------------
    for (int i = tid; i <= NS; i += NTHREADS) offs[i] = 0;
    __syncthreads();

    // ---- 2. vectorized load, histogram, alpha partials ----------------------
    float lx[IPT], lw[IPT];
    float pxw = 0.f, pw = 0.f;
    {
        const float4* gx4 = (const float4*)gx;
        const float4* gw4 = (const float4*)gw;
#pragma unroll
        for (int v = 0; v < IPT / 4; v++) {
            float4 X = gx4[tid + v * NTHREADS];
            float4 W = gw4[tid + v * NTHREADS];
            lx[v*4+0] = X.x; lx[v*4+1] = X.y; lx[v*4+2] = X.z; lx[v*4+3] = X.w;
            lw[v*4+0] = W.x; lw[v*4+1] = W.y; lw[v*4+2] = W.z; lw[v*4+3] = W.w;
        }
#pragma unroll
        for (int i = 0; i < IPT; i++) {
            pxw += lx[i] * lw[i]; pw += lw[i];
            int b = (int)(lx[i] * 8192.0f);    // exact order-preserving bucket
            if (b > NS - 1) b = NS - 1;
            atomicAdd(&offs[b + 1], 1);
        }
    }
    {
        int lane = tid & 31, wid = tid >> 5;
        float a = pxw, b = pw;
#pragma unroll
        for (int d = 16; d > 0; d >>= 1) {
            a += __shfl_down_sync(0xffffffffu, a, d);
            b += __shfl_down_sync(0xffffffffu, b, d);
        }
        if (lane == 0) { s_pf[wid] = a; s_pf2[wid] = b; }
        __syncthreads();                       // also fences histogram atomics
        if (tid == 0) {
            float sa = 0.f, sb = 0.f;
#pragma unroll
            for (int k = 0; k < 32; k++) { sa += s_pf[k]; sb += s_pf2[k]; }
            s_alpha = sa / sb - 0.5f;
        }
    }

    // ---- 3. exclusive scan of counts -> bucket START offsets ----------------
    {
        int c[IPT]; int runc = 0;
#pragma unroll
        for (int j = 0; j < IPT; j++) {
            runc += offs[1 + tid * IPT + j];
            c[j] = runc;
        }
        int exc = block_excl_scan_int(runc, tid, s_pi);
#pragma unroll
        for (int j = 0; j < IPT; j++) offs[1 + tid * IPT + j] = exc + c[j];
        __syncthreads();
    }

    // ---- 4. scatter: offs consumed in place as cursors ----------------------
    // post-scatter offs[b] = END of bucket b: bucket b = [b?offs[b-1]:0, offs[b])
    {
#pragma unroll
        for (int i = 0; i < IPT; i++) {
            float x = lx[i];
            int b = (int)(x * 8192.0f);
            if (b > NS - 1) b = NS - 1;
            int pos = atomicAdd(&offs[b], 1);
            xs[pos] = x;
            cw[pos] = lw[i];
        }
        __syncthreads();
    }

    // ---- 5. per-bucket insertion sort (avg occupancy 1) ---------------------
    for (int b = tid; b < NS; b += NTHREADS) {
        int s = b ? offs[b - 1] : 0;
        int e = offs[b];
        for (int i = s + 1; i < e; i++) {
            float kx = xs[i], kv = cw[i];
            int j = i - 1;
            while (j >= s && xs[j] > kx) { xs[j+1] = xs[j]; cw[j+1] = cw[j]; j--; }
            xs[j+1] = kx; cw[j+1] = kv;
        }
    }
    __syncthreads();

    // ---- 6. cumsum of sorted weights -> cdf (in place) ----------------------
    {
        float v[IPT]; float runf = 0.f;
#pragma unroll
        for (int j = 0; j < IPT; j++) { runf += cw[tid * IPT + j]; v[j] = runf; }
        float excf = block_excl_scan_float(runf, tid, s_pf);
#pragma unroll
        for (int j = 0; j < IPT; j++) cw[tid * IPT + j] = excf + v[j];
        __syncthreads();
    }

    // ---- 7a. overlap: stashing mini-bisections || speculative raster --------
    const float alpha_r = s_alpha;
    int spec_lo, spec_hi;
    {
        int est = (int)((1.0f - alpha_r) * (24575.0f / 3.0f));
        spec_lo = est - 288;         if (spec_lo < 0) spec_lo = 0;
        spec_hi = est + NS + 576;    if (spec_hi > NG - 1) spec_hi = NG - 1;
        if (tid == 0)
            s_jlo = bisect_eval_stash(ecdf, xs, cw, offs, 0.0f - alpha_r);
        else if (tid == 32)
            s_jhi = bisect_eval_stash(ecdf, xs, cw, offs,
                                      (float)(NREF - 1) * INVN - alpha_r);
        else if (tid >= 64) {
            for (int j = spec_lo + (tid - 64); j <= spec_hi; j += NTHREADS - 64)
                ecdf[j] = eval_ecdf(j, xs, cw, offs);
        }
    }
    __syncthreads();

    // ---- 7b. gap fill (uniformly skipped when spec window covers) -----------
    {
        int jstart = s_jlo - 1; if (jstart < 0) jstart = 0;
        int jend   = s_jhi;     if (jend > NG - 1) jend = NG - 1;
        bool need_fill = (jstart < spec_lo) || (jend > spec_hi);  // block-uniform
        if (need_fill) {
            for (int j = jstart + tid; j < spec_lo; j += NTHREADS)
                ecdf[j] = eval_ecdf(j, xs, cw, offs);
            for (int j = spec_hi + 1 + tid; j <= jend; j += NTHREADS)
                ecdf[j] = eval_ecdf(j, xs, cw, offs);
            __syncthreads();
        }
    }

    // ---- 8. invert CDF: bracketed exact inversion ---------------------------
    // Fence landings bracket the 7 intermediate ones (landings monotone in y).
    // Lane31's upper fence = next warp's lane0 posA, published through shared
    // memory (identical value, no second bisect). Safe bracket => count sweep
    // with phase-rotated iteration (order-independent count; rotation kills
    // the systematic 8-way LDS bank conflicts). Unsafe => exact fallback.
    const int k0 = tid * KPT;
    {
        const int lane = tid & 31, wid = tid >> 5;
        float y0 = (float)k0 * INVN - alpha_r;
        int posA = full_bisect(ecdf, y0);
        if (lane == 0) s_wfence[wid] = posA;
        if (tid == 0)  s_wfence[32] = s_jhi;   // sentinel: landing of y(NREF-1)
        int posB = __shfl_down_sync(0xffffffffu, posA, 1);
        __syncthreads();
        if (lane == 31) posB = s_wfence[wid + 1];

        float yq[KPT];
#pragma unroll
        for (int q = 1; q < KPT; q++)
            yq[q] = (float)(k0 + q) * INVN - alpha_r;

        int pos[KPT];
        pos[0] = posA;
        int w = posB - posA;
        bool unsafe = (8192  >= posA && 8192  <= posB) ||
                      (16384 >= posA && 16384 <= posB) ||
                      (NG - 1 >= posA && NG - 1 <= posB);
        if (!unsafe && w <= 64) {
            // count sweep (order-independent): phase-rotate to avoid conflicts
            int ph = (w >= 8) ? ((lane >> 2) & 7) : 0;
            int cnt[KPT];
#pragma unroll
            for (int q = 1; q < KPT; q++) cnt[q] = 0;
            for (int k = 0; k < w; k++) {
                int kk = k + ph; if (kk >= w) kk -= w;
                float e = ecdf[posA + kk];
#pragma unroll
                for (int q = 1; q < KPT; q++) cnt[q] += (e < yq[q]) ? 1 : 0;
            }
#pragma unroll
            for (int q = 1; q < KPT; q++) pos[q] = posA + cnt[q];
        } else if (!unsafe) {
            // wide monotone bracket: restricted bisection (identical landing)
            int hi_q[KPT];
#pragma unroll
            for (int q = 1; q < KPT; q++) { pos[q] = posA; hi_q[q] = posB; }
            while (w > 0) {
#pragma unroll
                for (int q = 1; q < KPT; q++) {
                    if (pos[q] < hi_q[q]) {
                        int mid = (pos[q] + hi_q[q]) >> 1;
                        bool c = ecdf[mid] < yq[q];
                        pos[q]  = c ? mid + 1 : pos[q];
                        hi_q[q] = c ? hi_q[q] : mid;
                    }
                }
                w >>= 1;
            }
        } else {
            // bracket touches a possible non-monotone index: exact fallback
#pragma unroll
            for (int q = 1; q < KPT; q++)
                pos[q] = full_bisect(ecdf, yq[q]);
        }

        float4 outv[KPT / 4];
        float* outf = (float*)outv;
#pragma unroll
        for (int q = 0; q < KPT; q++) {
            int k = k0 + q;
            float xk = (float)k * INVN;
            float yv = xk - alpha_r;
            int idx = pos[q] - 1;
            idx = idx < 0 ? 0 : (idx > NG - 2 ? NG - 2 : idx);
            float e0 = ecdf[idx], e1 = ecdf[idx + 1];
            float xn0 = fmaf((float)idx,       STEPG, -1.0f);
            float xn1 = fmaf((float)(idx + 1), STEPG, -1.0f);
            float t = __fdividef(yv - e0, e1 - e0);
            outf[q] = fmaf(t, xn1 - xn0, xn0) - xk;
        }
        float4* hv = (float4*)(hout + k0);
        hv[0] = outv[0];
        hv[1] = outv[1];
    }

    // ---- 9. fused distance (2nd finisher per row) ---------------------------
    __threadfence();
    __syncthreads();                           // all h writes of block done
    if (tid == 0) {
        int old = atomicAdd(&g_done[row], 1);
        s_second = (old == 1);
        if (old == 1) g_done[row] = 0;         // self-reset for graph replays
        s_last = 0;
    }
    __syncthreads();
    if (s_second) {
        __threadfence();                       // acquire partner's h writes
        const float* hA = g_h + (size_t)row * NS;
        const float* hB = g_h + (size_t)(LROWS + row) * NS;
        float4 a0 = *(const float4*)(hA + k0);
        float4 a1 = *(const float4*)(hA + k0 + 4);
        float4 b0 = *(const float4*)(hB + k0);
        float4 b1 = *(const float4*)(hB + k0 + 4);
        float acc = 0.f;
        {
            const float* pa = (const float*)&a0;
            const float* pb = (const float*)&b0;
#pragma unroll
            for (int i = 0; i < 4; i++) {
                float d = fabsf(pb[i] - pa[i]);
                float m = fminf(d, 1.0f - d);
                acc = fmaf(m, m, acc);
            }
            pa = (const float*)&a1; pb = (const float*)&b1;
#pragma unroll
            for (int i = 0; i < 4; i++) {
                float d = fabsf(pb[i] - pa[i]);
                float m = fminf(d, 1.0f - d);
                acc = fmaf(m, m, acc);
            }
        }
        int lane = tid & 31, wid = tid >> 5;
#pragma unroll
        for (int d = 16; d > 0; d >>= 1)
            acc += __shfl_down_sync(0xffffffffu, acc, d);
        if (lane == 0) s_pf[wid] = acc;
        __syncthreads();
        if (tid == 0) {
            float s = 0.f;
#pragma unroll
            for (int k = 0; k < 32; k++) s += s_pf[k];
            g_rowsum[row] = s;
            __threadfence();                   // release rowsum
            int old2 = atomicAdd(&g_nrows, 1);
            s_last = (old2 == LROWS - 1);
            if (s_last) g_nrows = 0;           // self-reset for graph replays
        }
        __syncthreads();

        // ---- 10. fused finalize (the very last finisher block) --------------
        if (s_last) {
            __threadfence();                   // acquire all rowsums
            float* red = (float*)smem_raw;     // reuse smem (xs region)
            if (tid < LROWS) red[tid] = g_rowsum[tid];
            __syncthreads();
            for (int s = LROWS / 2; s > 0; s >>= 1) {
                if (tid < s) red[tid] += red[tid + s];
                __syncthreads();
            }
            if (tid == 0) out[0] = sqrtf(red[0] / (float)LROWS);
        }
    }
}

extern "C" void kernel_launch(void* const* d_in, const int* in_sizes, int n_in,
                              void* d_out, int out_size)
{
    const float* x1 = (const float*)d_in[0];
    const float* w1 = (const float*)d_in[1];
    const float* x2 = (const float*)d_in[2];
    const float* w2 = (const float*)d_in[3];
    float* out = (float*)d_out;

    size_t dyn = (size_t)(2 * NS) * sizeof(float)
               + (size_t)(NS + 1) * sizeof(int)
               + (size_t)NG * sizeof(float);   // 196612 B

    cudaFuncSetAttribute(lcot_emb_kernel,
                         cudaFuncAttributeMaxDynamicSharedMemorySize, (int)dyn);

    lcot_emb_kernel<<<2 * LROWS, NTHREADS, dyn>>>(x1, w1, x2, w2, out);
}